// round 5
// baseline (speedup 1.0000x reference)
#include <cuda_runtime.h>
#include <cuda_bf16.h>
#include <cstdint>
#include <math.h>

// ---------------- problem constants ----------------
#define N_DRUGS   4000
#define N_GENES   4264
#define NNODES    8264
#define IN_DIM    1613
#define DIM1      1340
#define DIM2      920
#define DIM3      740
#define N_REL     4
#define N_EDGES   100000
#define NSEG      (NNODES * N_REL)     // 33056

#define MPAD      8320                 // 65 * 128
#define KP1       1664                 // pad(1613, 64)
#define KP2       1344                 // pad(1340, 64)
#define KP3       960                  // pad(920, 64)
#define KC1       (5 * KP1)            // 8320
#define KC2       (5 * KP2)            // 6720
#define NP1       1408
#define NP2       1024
#define NP3       768

// K-split points (multiples of 64)
#define KS1       4160                 // KC1/2 (65 chunks each)
#define KS2A      3328                 // 52 chunks
#define KS2B      (KC2 - KS2A)         // 3392 = 53 chunks

// ---------------- device scratch ----------------
__device__ __nv_bfloat16 g_Xcat_hi[(size_t)MPAD * KC1];
__device__ __nv_bfloat16 g_Xcat_lo[(size_t)MPAD * KC1];
__device__ __nv_bfloat16 g_W1hi[(size_t)NP1 * KC1];
__device__ __nv_bfloat16 g_W1lo[(size_t)NP1 * KC1];
__device__ float         g_A1[(size_t)NNODES * DIM1];
__device__ __nv_bfloat16 g_A1cat_hi[(size_t)MPAD * KC2];
__device__ __nv_bfloat16 g_A1cat_lo[(size_t)MPAD * KC2];
__device__ __nv_bfloat16 g_W2hi[(size_t)NP2 * KC2];
__device__ __nv_bfloat16 g_W2lo[(size_t)NP2 * KC2];
__device__ __nv_bfloat16 g_A2hi[(size_t)MPAD * KP3];
__device__ __nv_bfloat16 g_A2lo[(size_t)MPAD * KP3];
__device__ __nv_bfloat16 g_W3hi[(size_t)NP3 * KP3];
__device__ __nv_bfloat16 g_W3lo[(size_t)NP3 * KP3];
__device__ float         g_Ctmp[(size_t)MPAD * NP1];   // 46.8 MB (covers NP2 too)
__device__ int g_cnt[NSEG];
__device__ int g_seg_start[NSEG + 1];
__device__ int g_cursor[NSEG];
__device__ int g_esrc[N_EDGES];

// ---------------- PTX helpers (plain sm_80+ instructions only) ----------------
__device__ __forceinline__ uint32_t smem_to_u32(const void* p) {
    uint32_t a;
    asm("{ .reg .u64 t; cvta.to.shared.u64 t, %1; cvt.u32.u64 %0, t; }" : "=r"(a) : "l"(p));
    return a;
}
#define CP_ASYNC16(dst, src) \
    asm volatile("cp.async.cg.shared.global [%0], [%1], 16;" :: "r"(dst), "l"(src) : "memory")
#define CP_ASYNC_COMMIT() asm volatile("cp.async.commit_group;" ::: "memory")
#define CP_ASYNC_WAIT(n)  asm volatile("cp.async.wait_group %0;" :: "n"(n) : "memory")

__device__ __forceinline__ void ldsm4(uint32_t (&r)[4], uint32_t addr) {
    asm volatile("ldmatrix.sync.aligned.m8n8.x4.shared.b16 {%0,%1,%2,%3}, [%4];"
                 : "=r"(r[0]), "=r"(r[1]), "=r"(r[2]), "=r"(r[3]) : "r"(addr));
}
__device__ __forceinline__ void mma16816(float (&d)[4], const uint32_t (&a)[4],
                                         uint32_t b0, uint32_t b1) {
    asm volatile(
        "mma.sync.aligned.m16n8k16.row.col.f32.bf16.bf16.f32 "
        "{%0,%1,%2,%3}, {%4,%5,%6,%7}, {%8,%9}, {%0,%1,%2,%3};"
        : "+f"(d[0]), "+f"(d[1]), "+f"(d[2]), "+f"(d[3])
        : "r"(a[0]), "r"(a[1]), "r"(a[2]), "r"(a[3]), "r"(b0), "r"(b1));
}
#define SWZ(off) ((off) ^ (((off) >> 3) & 0x70))

// ---------------- prep: x -> Xcat root slot (bf16 hi/lo) ----------------
__global__ void xfill_kernel(const float* __restrict__ x, const float* __restrict__ gene)
{
    size_t i = (size_t)blockIdx.x * blockDim.x + threadIdx.x;
    const size_t TOT = (size_t)NNODES * IN_DIM;
    if (i >= TOT) return;
    int node = (int)(i / IN_DIM);
    int k = (int)(i % IN_DIM);
    float v = (node < N_DRUGS) ? x[(size_t)node * IN_DIM + k]
                               : gene[(size_t)(node - N_DRUGS) * IN_DIM + k];
    __nv_bfloat16 hi = __float2bfloat16(v);
    size_t o = (size_t)node * KC1 + 4 * KP1 + k;
    g_Xcat_hi[o] = hi;
    g_Xcat_lo[o] = __float2bfloat16(v - __bfloat162float(hi));
}

// transpose W[K][N] (z slabs) -> Wcat[n][z*Kpad + k] hi/lo, zero-padded
__global__ void transpose_split_kernel(const float* __restrict__ Wrel,
                                       const float* __restrict__ Wroot,
                                       __nv_bfloat16* __restrict__ Thi,
                                       __nv_bfloat16* __restrict__ Tlo,
                                       int K, int N, int Kpad, int KC, int Npad)
{
    __shared__ float t[32][33];
    int z = blockIdx.z;
    const float* W = (Wrel != nullptr && z < N_REL) ? (Wrel + (size_t)z * K * N) : Wroot;
    int k0 = blockIdx.x * 32;
    int n0 = blockIdx.y * 32;
    int tx = threadIdx.x, ty = threadIdx.y;
#pragma unroll
    for (int i = 0; i < 4; i++) {
        int k = k0 + ty + i * 8;
        int n = n0 + tx;
        t[ty + i * 8][tx] = (k < K && n < N) ? W[(size_t)k * N + n] : 0.f;
    }
    __syncthreads();
#pragma unroll
    for (int i = 0; i < 4; i++) {
        int n = n0 + ty + i * 8;
        int kk = k0 + tx;
        float v = t[tx][ty + i * 8];
        __nv_bfloat16 hi = __float2bfloat16(v);
        size_t o = (size_t)n * KC + (size_t)z * Kpad + kk;
        Thi[o] = hi;
        Tlo[o] = __float2bfloat16(v - __bfloat162float(hi));
    }
}

// ---------------- edge preprocessing ----------------
__global__ void zero_cnt_kernel()
{
    int i = blockIdx.x * blockDim.x + threadIdx.x;
    if (i < NSEG) g_cnt[i] = 0;
}
__global__ void count_kernel(const int* __restrict__ edge_index, const int* __restrict__ edge_type)
{
    int e = blockIdx.x * blockDim.x + threadIdx.x;
    if (e >= N_EDGES) return;
    atomicAdd(&g_cnt[edge_index[N_EDGES + e] * N_REL + edge_type[e]], 1);
}
__global__ void scan_kernel()
{
    __shared__ int part[1024];
    const int CHK = (NSEG + 1023) / 1024;
    int tid = threadIdx.x;
    int degs[CHK];
    int mysum = 0;
#pragma unroll
    for (int i = 0; i < CHK; i++) {
        int d = tid * CHK + i;
        int dg = (d < NSEG) ? g_cnt[d] : 0;
        degs[i] = dg;
        mysum += dg;
    }
    part[tid] = mysum;
    __syncthreads();
    if (tid == 0) {
        int run = 0;
        for (int t = 0; t < 1024; t++) { int v = part[t]; part[t] = run; run += v; }
        g_seg_start[NSEG] = run;
    }
    __syncthreads();
    int off = part[tid];
#pragma unroll
    for (int i = 0; i < CHK; i++) {
        int d = tid * CHK + i;
        if (d < NSEG) { g_seg_start[d] = off; g_cursor[d] = off; off += degs[i]; }
    }
}
__global__ void fill_kernel(const int* __restrict__ edge_index, const int* __restrict__ edge_type)
{
    int e = blockIdx.x * blockDim.x + threadIdx.x;
    if (e >= N_EDGES) return;
    int seg = edge_index[N_EDGES + e] * N_REL + edge_type[e];
    int pos = atomicAdd(&g_cursor[seg], 1);
    g_esrc[pos] = edge_index[e];
}

// ---------------- segment-mean aggregation, emits bf16 hi/lo ----------------
template <int CH>
__global__ void agg_seg_kernel(const float* __restrict__ src0, const float* __restrict__ src1,
                               int splitRow, int D, int Kpad, int KC,
                               __nv_bfloat16* __restrict__ outHi, __nv_bfloat16* __restrict__ outLo)
{
    int seg = blockIdx.x;
    int s = g_seg_start[seg];
    int e = g_seg_start[seg + 1];
    if (s == e) return;
    int tid = threadIdx.x;
    float acc[CH];
#pragma unroll
    for (int j = 0; j < CH; j++) acc[j] = 0.f;
    for (int p = s; p < e; p++) {
        int sn = g_esrc[p];
        const float* row = (sn < splitRow) ? (src0 + (size_t)sn * D)
                                           : (src1 + (size_t)(sn - splitRow) * D);
#pragma unroll
        for (int j = 0; j < CH; j++) {
            int o = tid + j * 256;
            if (o < D) acc[j] += row[o];
        }
    }
    float inv = 1.0f / (float)(e - s);
    int node = seg >> 2, rel = seg & 3;
    size_t base = (size_t)node * KC + (size_t)rel * Kpad;
#pragma unroll
    for (int j = 0; j < CH; j++) {
        int o = tid + j * 256;
        if (o < D) {
            float v = acc[j] * inv;
            __nv_bfloat16 hi = __float2bfloat16(v);
            outHi[base + o] = hi;
            outLo[base + o] = __float2bfloat16(v - __bfloat162float(hi));
        }
    }
}

// ---------------- mma.sync bf16-split GEMM with K-split passes ----------------
// Per launch computes partial C over Klen columns (A/B pointers pre-offset).
// Craw != 0  : write raw fp32 partials to Craw (padded stride NoutPad), no bias.
// Craw == 0  : final pass: v = acc (+ Cadd) + bias -> relu -> outF / outHi,outLo.
#define TILE_B  (128 * 128)
#define STAGE_B (4 * TILE_B)         // 64 KB
#define GEMM_SMEM (3 * STAGE_B)      // 192 KB

__global__ void __launch_bounds__(256, 1)
gemm_mma_kernel(const __nv_bfloat16* __restrict__ Ahi, const __nv_bfloat16* __restrict__ Alo,
                const __nv_bfloat16* __restrict__ Bhi, const __nv_bfloat16* __restrict__ Blo,
                int Kstride, int Klen, int Nout, int NoutPad,
                const float* __restrict__ bias,
                float* __restrict__ Craw, const float* __restrict__ Cadd,
                float* __restrict__ outF,
                __nv_bfloat16* __restrict__ outHi, __nv_bfloat16* __restrict__ outLo,
                int strideO, int colOff)
{
    extern __shared__ char dsm[];
    const uint32_t sbase = smem_to_u32(dsm);
    const int tid = threadIdx.x;
    const int lane = tid & 31;
    const int wid = tid >> 5;
    const int m_off = (wid >> 2) * 64;
    const int n_off = (wid & 3) * 32;
    const int m0 = blockIdx.y * 128;
    const int n0 = blockIdx.x * 128;

    const int arow = lane & 15;
    const uint32_t xorv = (uint32_t)(arow & 7) << 4;
    uint32_t colp[4];
#pragma unroll
    for (int ks = 0; ks < 4; ks++)
        colp[ks] = ((uint32_t)(ks * 32 + ((lane >> 4) * 16))) ^ xorv;
    uint32_t rowA[4], rowB[2];
#pragma unroll
    for (int mi = 0; mi < 4; mi++) rowA[mi] = (uint32_t)(m_off + mi * 16 + arow) * 128u;
#pragma unroll
    for (int nj = 0; nj < 2; nj++) rowB[nj] = (uint32_t)(n_off + nj * 16 + arow) * 128u;

    float acc[4][4][4];
#pragma unroll
    for (int mi = 0; mi < 4; mi++)
#pragma unroll
        for (int nt = 0; nt < 4; nt++)
#pragma unroll
            for (int q = 0; q < 4; q++) acc[mi][nt][q] = 0.f;

    const int chunks = Klen >> 6;

    auto load_stage = [&](int slot, int c) {
        const int k0 = c << 6;
        const uint32_t base = sbase + (uint32_t)slot * STAGE_B;
#pragma unroll
        for (int i = 0; i < 16; i++) {
            int idx = tid + i * 256;
            int t = idx >> 10;
            int r = (idx >> 3) & 127;
            int j = idx & 7;
            const __nv_bfloat16* src = (t == 0) ? Ahi : (t == 1) ? Alo : (t == 2) ? Bhi : Blo;
            int row0 = (t < 2) ? m0 : n0;
            CP_ASYNC16(base + (uint32_t)t * TILE_B + SWZ((uint32_t)(r * 128 + j * 16)),
                       (const void*)(src + (size_t)(row0 + r) * Kstride + k0 + j * 8));
        }
        CP_ASYNC_COMMIT();
    };

    if (chunks > 0) load_stage(0, 0);
    if (chunks > 1) load_stage(1, 1);
    if (chunks > 2) load_stage(2, 2);

    for (int c = 0; c < chunks; c++) {
        int ahead = chunks - 1 - c;
        if (ahead >= 2)      CP_ASYNC_WAIT(2);
        else if (ahead == 1) CP_ASYNC_WAIT(1);
        else                 CP_ASYNC_WAIT(0);
        __syncthreads();

        const uint32_t sb = sbase + (uint32_t)((c % 3)) * STAGE_B;
#pragma unroll
        for (int ks = 0; ks < 4; ks++) {
            uint32_t ah[4][4], al[4][4];
            uint32_t bh[4][2], bl[4][2];
#pragma unroll
            for (int mi = 0; mi < 4; mi++) {
                ldsm4(ah[mi], sb + rowA[mi] + colp[ks]);
                ldsm4(al[mi], sb + TILE_B + rowA[mi] + colp[ks]);
            }
#pragma unroll
            for (int nj = 0; nj < 2; nj++) {
                uint32_t t4[4];
                ldsm4(t4, sb + 2 * TILE_B + rowB[nj] + colp[ks]);
                bh[2 * nj][0] = t4[0]; bh[2 * nj][1] = t4[2];
                bh[2 * nj + 1][0] = t4[1]; bh[2 * nj + 1][1] = t4[3];
                ldsm4(t4, sb + 3 * TILE_B + rowB[nj] + colp[ks]);
                bl[2 * nj][0] = t4[0]; bl[2 * nj][1] = t4[2];
                bl[2 * nj + 1][0] = t4[1]; bl[2 * nj + 1][1] = t4[3];
            }
#pragma unroll
            for (int mi = 0; mi < 4; mi++)
#pragma unroll
                for (int nt = 0; nt < 4; nt++) {
                    mma16816(acc[mi][nt], ah[mi], bh[nt][0], bh[nt][1]);
                    mma16816(acc[mi][nt], ah[mi], bl[nt][0], bl[nt][1]);
                    mma16816(acc[mi][nt], al[mi], bh[nt][0], bh[nt][1]);
                }
        }
        __syncthreads();
        if (c + 3 < chunks) load_stage(c % 3, c + 3);
    }

    // ---- epilogue ----
    float* sC = (float*)dsm;
#pragma unroll
    for (int mi = 0; mi < 4; mi++)
#pragma unroll
        for (int nt = 0; nt < 4; nt++) {
            int r0 = m_off + mi * 16 + (lane >> 2);
            int c0 = n_off + nt * 8 + (lane & 3) * 2;
            *(float2*)&sC[r0 * 132 + c0] = make_float2(acc[mi][nt][0], acc[mi][nt][1]);
            *(float2*)&sC[(r0 + 8) * 132 + c0] = make_float2(acc[mi][nt][2], acc[mi][nt][3]);
        }
    __syncthreads();

    if (Craw) {
        // raw partial pass: unbounded padded write
#pragma unroll
        for (int i = 0; i < 64; i++) {
            int idx = tid + i * 256;
            int r = idx >> 7, cc = idx & 127;
            Craw[(size_t)(m0 + r) * NoutPad + n0 + cc] = sC[r * 132 + cc];
        }
        return;
    }
#pragma unroll
    for (int i = 0; i < 64; i++) {
        int idx = tid + i * 256;
        int r = idx >> 7, cc = idx & 127;
        int gm = m0 + r, gn = n0 + cc;
        if (gm < NNODES && gn < Nout) {
            float v = sC[r * 132 + cc];
            if (Cadd) v += Cadd[(size_t)gm * NoutPad + gn];
            v = fmaxf(v + bias[gn], 0.f);
            if (outF) outF[(size_t)gm * Nout + gn] = v;
            if (outHi) {
                __nv_bfloat16 hi = __float2bfloat16(v);
                size_t o = (size_t)gm * strideO + colOff + gn;
                outHi[o] = hi;
                outLo[o] = __float2bfloat16(v - __bfloat162float(hi));
            }
        }
    }
}

// ---------------- final head: logits + log_softmax ----------------
__global__ void logits_kernel(const float* __restrict__ emb,
                              const float* __restrict__ lin2_w,
                              const float* __restrict__ lin2_b,
                              float* __restrict__ out)
{
    int gtid = blockIdx.x * blockDim.x + threadIdx.x;
    int node = gtid >> 5;
    int lane = gtid & 31;
    if (node >= NNODES) return;
    const float* e = emb + (size_t)node * DIM3;
    float s0 = 0.f, s1 = 0.f;
    for (int k = lane; k < DIM3; k += 32) {
        float v = e[k];
        s0 = fmaf(v, lin2_w[2 * k + 0], s0);
        s1 = fmaf(v, lin2_w[2 * k + 1], s1);
    }
#pragma unroll
    for (int o = 16; o; o >>= 1) {
        s0 += __shfl_down_sync(0xffffffffu, s0, o);
        s1 += __shfl_down_sync(0xffffffffu, s1, o);
    }
    if (lane == 0) {
        s0 += lin2_b[0];
        s1 += lin2_b[1];
        float m = fmaxf(s0, s1);
        float l = m + logf(expf(s0 - m) + expf(s1 - m));
        out[2 * node + 0] = s0 - l;
        out[2 * node + 1] = s1 - l;
    }
}

// ---------------- launch ----------------
extern "C" void kernel_launch(void* const* d_in, const int* in_sizes, int n_in,
                              void* d_out, int out_size)
{
    const float* x       = (const float*)d_in[0];
    const float* gene    = (const float*)d_in[1];
    const float* w_rel1  = (const float*)d_in[2];
    const float* root1   = (const float*)d_in[3];
    const float* b1      = (const float*)d_in[4];
    const float* w_rel2  = (const float*)d_in[5];
    const float* root2   = (const float*)d_in[6];
    const float* b2      = (const float*)d_in[7];
    const float* lin1_w  = (const float*)d_in[8];
    const float* lin1_b  = (const float*)d_in[9];
    const float* lin2_w  = (const float*)d_in[10];
    const float* lin2_b  = (const float*)d_in[11];
    const int*   edge_index = (const int*)d_in[12];
    const int*   edge_type  = (const int*)d_in[13];
    float* out = (float*)d_out;

    __nv_bfloat16 *Xch, *Xcl, *W1h, *W1l, *A1ch, *A1cl, *W2h, *W2l, *A2h, *A2l, *W3h, *W3l;
    float *A1, *Ctmp;
    cudaGetSymbolAddress((void**)&Xch, g_Xcat_hi);  cudaGetSymbolAddress((void**)&Xcl, g_Xcat_lo);
    cudaGetSymbolAddress((void**)&W1h, g_W1hi);     cudaGetSymbolAddress((void**)&W1l, g_W1lo);
    cudaGetSymbolAddress((void**)&A1, g_A1);
    cudaGetSymbolAddress((void**)&A1ch, g_A1cat_hi); cudaGetSymbolAddress((void**)&A1cl, g_A1cat_lo);
    cudaGetSymbolAddress((void**)&W2h, g_W2hi);     cudaGetSymbolAddress((void**)&W2l, g_W2lo);
    cudaGetSymbolAddress((void**)&A2h, g_A2hi);     cudaGetSymbolAddress((void**)&A2l, g_A2lo);
    cudaGetSymbolAddress((void**)&W3h, g_W3hi);     cudaGetSymbolAddress((void**)&W3l, g_W3lo);
    cudaGetSymbolAddress((void**)&Ctmp, g_Ctmp);

    cudaFuncSetAttribute(gemm_mma_kernel, cudaFuncAttributeMaxDynamicSharedMemorySize, GEMM_SMEM);

    // 1) weight transposes + splits
    {
        dim3 tb(32, 8);
        transpose_split_kernel<<<dim3(KP1 / 32, NP1 / 32, 5), tb>>>(w_rel1, root1, W1h, W1l, IN_DIM, DIM1, KP1, KC1, NP1);
        transpose_split_kernel<<<dim3(KP2 / 32, NP2 / 32, 5), tb>>>(w_rel2, root2, W2h, W2l, DIM1, DIM2, KP2, KC2, NP2);
        transpose_split_kernel<<<dim3(KP3 / 32, NP3 / 32, 1), tb>>>(nullptr, lin1_w, W3h, W3l, DIM2, DIM3, KP3, KP3, NP3);
    }
    // 2) edge preprocessing
    zero_cnt_kernel<<<(NSEG + 255) / 256, 256>>>();
    count_kernel<<<(N_EDGES + 255) / 256, 256>>>(edge_index, edge_type);
    scan_kernel<<<1, 1024>>>();
    fill_kernel<<<(N_EDGES + 255) / 256, 256>>>(edge_index, edge_type);

    // 3) layer-1 input assembly
    {
        size_t tot = (size_t)NNODES * IN_DIM;
        xfill_kernel<<<(unsigned)((tot + 255) / 256), 256>>>(x, gene);
    }
    agg_seg_kernel<7><<<NSEG, 256>>>(x, gene, N_DRUGS, IN_DIM, KP1, KC1, Xch, Xcl);

    // 4) layer-1 GEMM, K split into two L2-resident passes
    dim3 g1(NP1 / 128, MPAD / 128);
    gemm_mma_kernel<<<g1, 256, GEMM_SMEM>>>(
        Xch, Xcl, W1h, W1l, KC1, KS1, DIM1, NP1, nullptr,
        Ctmp, nullptr, nullptr, nullptr, nullptr, 0, 0);
    gemm_mma_kernel<<<g1, 256, GEMM_SMEM>>>(
        Xch + KS1, Xcl + KS1, W1h + KS1, W1l + KS1, KC1, KC1 - KS1, DIM1, NP1, b1,
        nullptr, Ctmp, A1, A1ch, A1cl, KC2, 4 * KP2);

    // 5) layer-2 input assembly
    agg_seg_kernel<6><<<NSEG, 256>>>(A1, A1, NNODES, DIM1, KP2, KC2, A1ch, A1cl);

    // 6) layer-2 GEMM, K split
    dim3 g2(NP2 / 128, MPAD / 128);
    gemm_mma_kernel<<<g2, 256, GEMM_SMEM>>>(
        A1ch, A1cl, W2h, W2l, KC2, KS2A, DIM2, NP2, nullptr,
        Ctmp, nullptr, nullptr, nullptr, nullptr, 0, 0);
    gemm_mma_kernel<<<g2, 256, GEMM_SMEM>>>(
        A1ch + KS2A, A1cl + KS2A, W2h + KS2A, W2l + KS2A, KC2, KS2B, DIM2, NP2, b2,
        nullptr, Ctmp, nullptr, A2h, A2l, KP3, 0);

    // 7) lin1 (single pass) -> emb in output buffer
    float* emb = out + 2 * NNODES;
    gemm_mma_kernel<<<dim3(NP3 / 128, MPAD / 128), 256, GEMM_SMEM>>>(
        A2h, A2l, W3h, W3l, KP3, KP3, DIM3, NP3, lin1_b,
        nullptr, nullptr, emb, nullptr, nullptr, 0, 0);

    // 8) lin2 + log_softmax
    logits_kernel<<<(NNODES * 32 + 255) / 256, 256>>>(emb, lin2_w, lin2_b, out);
}

// round 6
// speedup vs baseline: 1.1111x; 1.1111x over previous
#include <cuda_runtime.h>
#include <cuda_bf16.h>
#include <cstdint>
#include <math.h>

// ---------------- problem constants ----------------
#define N_DRUGS   4000
#define N_GENES   4264
#define NNODES    8264
#define IN_DIM    1613
#define DIM1      1340
#define DIM2      920
#define DIM3      740
#define N_REL     4
#define N_EDGES   100000
#define NSEG      (NNODES * N_REL)     // 33056

#define MPAD      8320                 // 65 * 128
#define KP1       1664                 // pad(1613, 64)
#define KP2       1344                 // pad(1340, 64)
#define KP3       960                  // pad(920, 64)
#define KC1       (5 * KP1)            // 8320
#define KC2       (5 * KP2)            // 6720
#define NP1       1408
#define NP2       1024
#define NP3       768

// ---------------- device scratch ----------------
__device__ __nv_bfloat16 g_Xcat_hi[(size_t)MPAD * KC1];
__device__ __nv_bfloat16 g_Xcat_lo[(size_t)MPAD * KC1];
__device__ __nv_bfloat16 g_W1hi[(size_t)NP1 * KC1];
__device__ __nv_bfloat16 g_W1lo[(size_t)NP1 * KC1];
__device__ float         g_A1[(size_t)NNODES * DIM1];
__device__ __nv_bfloat16 g_A1cat_hi[(size_t)MPAD * KC2];
__device__ __nv_bfloat16 g_A1cat_lo[(size_t)MPAD * KC2];
__device__ __nv_bfloat16 g_W2hi[(size_t)NP2 * KC2];
__device__ __nv_bfloat16 g_W2lo[(size_t)NP2 * KC2];
__device__ __nv_bfloat16 g_A2hi[(size_t)MPAD * KP3];
__device__ __nv_bfloat16 g_A2lo[(size_t)MPAD * KP3];
__device__ __nv_bfloat16 g_W3hi[(size_t)NP3 * KP3];
__device__ __nv_bfloat16 g_W3lo[(size_t)NP3 * KP3];
__device__ int g_cnt[NSEG];
__device__ int g_seg_start[NSEG + 1];
__device__ int g_cursor[NSEG];
__device__ int g_esrc[N_EDGES];

// ---------------- PTX helpers (plain sm_80+ instructions only) ----------------
__device__ __forceinline__ uint32_t smem_to_u32(const void* p) {
    uint32_t a;
    asm("{ .reg .u64 t; cvta.to.shared.u64 t, %1; cvt.u32.u64 %0, t; }" : "=r"(a) : "l"(p));
    return a;
}
#define CP_ASYNC16(dst, src) \
    asm volatile("cp.async.cg.shared.global [%0], [%1], 16;" :: "r"(dst), "l"(src) : "memory")
#define CP_ASYNC_COMMIT() asm volatile("cp.async.commit_group;" ::: "memory")
#define CP_ASYNC_WAIT(n)  asm volatile("cp.async.wait_group %0;" :: "n"(n) : "memory")

__device__ __forceinline__ void ldsm4(uint32_t (&r)[4], uint32_t addr) {
    asm volatile("ldmatrix.sync.aligned.m8n8.x4.shared.b16 {%0,%1,%2,%3}, [%4];"
                 : "=r"(r[0]), "=r"(r[1]), "=r"(r[2]), "=r"(r[3]) : "r"(addr));
}
__device__ __forceinline__ void mma16816(float (&d)[4], const uint32_t (&a)[4],
                                         uint32_t b0, uint32_t b1) {
    asm volatile(
        "mma.sync.aligned.m16n8k16.row.col.f32.bf16.bf16.f32 "
        "{%0,%1,%2,%3}, {%4,%5,%6,%7}, {%8,%9}, {%0,%1,%2,%3};"
        : "+f"(d[0]), "+f"(d[1]), "+f"(d[2]), "+f"(d[3])
        : "r"(a[0]), "r"(a[1]), "r"(a[2]), "r"(a[3]), "r"(b0), "r"(b1));
}
#define SWZ(off) ((off) ^ (((off) >> 3) & 0x70))

// ---------------- prep: x -> Xcat root slot (bf16 hi/lo) ----------------
__global__ void xfill_kernel(const float* __restrict__ x, const float* __restrict__ gene)
{
    size_t i = (size_t)blockIdx.x * blockDim.x + threadIdx.x;
    const size_t TOT = (size_t)NNODES * IN_DIM;
    if (i >= TOT) return;
    int node = (int)(i / IN_DIM);
    int k = (int)(i % IN_DIM);
    float v = (node < N_DRUGS) ? x[(size_t)node * IN_DIM + k]
                               : gene[(size_t)(node - N_DRUGS) * IN_DIM + k];
    __nv_bfloat16 hi = __float2bfloat16(v);
    size_t o = (size_t)node * KC1 + 4 * KP1 + k;
    g_Xcat_hi[o] = hi;
    g_Xcat_lo[o] = __float2bfloat16(v - __bfloat162float(hi));
}

// transpose W[K][N] (z slabs) -> Wcat[n][z*Kpad + k] hi/lo, zero-padded
__global__ void transpose_split_kernel(const float* __restrict__ Wrel,
                                       const float* __restrict__ Wroot,
                                       __nv_bfloat16* __restrict__ Thi,
                                       __nv_bfloat16* __restrict__ Tlo,
                                       int K, int N, int Kpad, int KC, int Npad)
{
    __shared__ float t[32][33];
    int z = blockIdx.z;
    const float* W = (Wrel != nullptr && z < N_REL) ? (Wrel + (size_t)z * K * N) : Wroot;
    int k0 = blockIdx.x * 32;
    int n0 = blockIdx.y * 32;
    int tx = threadIdx.x, ty = threadIdx.y;
#pragma unroll
    for (int i = 0; i < 4; i++) {
        int k = k0 + ty + i * 8;
        int n = n0 + tx;
        t[ty + i * 8][tx] = (k < K && n < N) ? W[(size_t)k * N + n] : 0.f;
    }
    __syncthreads();
#pragma unroll
    for (int i = 0; i < 4; i++) {
        int n = n0 + ty + i * 8;
        int kk = k0 + tx;
        float v = t[tx][ty + i * 8];
        __nv_bfloat16 hi = __float2bfloat16(v);
        size_t o = (size_t)n * KC + (size_t)z * Kpad + kk;
        Thi[o] = hi;
        Tlo[o] = __float2bfloat16(v - __bfloat162float(hi));
    }
}

// ---------------- edge preprocessing ----------------
__global__ void zero_cnt_kernel()
{
    int i = blockIdx.x * blockDim.x + threadIdx.x;
    if (i < NSEG) g_cnt[i] = 0;
}
__global__ void count_kernel(const int* __restrict__ edge_index, const int* __restrict__ edge_type)
{
    int e = blockIdx.x * blockDim.x + threadIdx.x;
    if (e >= N_EDGES) return;
    atomicAdd(&g_cnt[edge_index[N_EDGES + e] * N_REL + edge_type[e]], 1);
}
__global__ void scan_kernel()
{
    __shared__ int part[1024];
    const int CHK = (NSEG + 1023) / 1024;
    int tid = threadIdx.x;
    int degs[CHK];
    int mysum = 0;
#pragma unroll
    for (int i = 0; i < CHK; i++) {
        int d = tid * CHK + i;
        int dg = (d < NSEG) ? g_cnt[d] : 0;
        degs[i] = dg;
        mysum += dg;
    }
    part[tid] = mysum;
    __syncthreads();
    if (tid == 0) {
        int run = 0;
        for (int t = 0; t < 1024; t++) { int v = part[t]; part[t] = run; run += v; }
        g_seg_start[NSEG] = run;
    }
    __syncthreads();
    int off = part[tid];
#pragma unroll
    for (int i = 0; i < CHK; i++) {
        int d = tid * CHK + i;
        if (d < NSEG) { g_seg_start[d] = off; g_cursor[d] = off; off += degs[i]; }
    }
}
__global__ void fill_kernel(const int* __restrict__ edge_index, const int* __restrict__ edge_type)
{
    int e = blockIdx.x * blockDim.x + threadIdx.x;
    if (e >= N_EDGES) return;
    int seg = edge_index[N_EDGES + e] * N_REL + edge_type[e];
    int pos = atomicAdd(&g_cursor[seg], 1);
    g_esrc[pos] = edge_index[e];
}

// ---------------- segment-mean aggregation, emits bf16 hi/lo ----------------
template <int CH>
__global__ void agg_seg_kernel(const float* __restrict__ src0, const float* __restrict__ src1,
                               int splitRow, int D, int Kpad, int KC,
                               __nv_bfloat16* __restrict__ outHi, __nv_bfloat16* __restrict__ outLo)
{
    int seg = blockIdx.x;
    int s = g_seg_start[seg];
    int e = g_seg_start[seg + 1];
    if (s == e) return;
    int tid = threadIdx.x;
    float acc[CH];
#pragma unroll
    for (int j = 0; j < CH; j++) acc[j] = 0.f;
    for (int p = s; p < e; p++) {
        int sn = g_esrc[p];
        const float* row = (sn < splitRow) ? (src0 + (size_t)sn * D)
                                           : (src1 + (size_t)(sn - splitRow) * D);
#pragma unroll
        for (int j = 0; j < CH; j++) {
            int o = tid + j * 256;
            if (o < D) acc[j] += row[o];
        }
    }
    float inv = 1.0f / (float)(e - s);
    int node = seg >> 2, rel = seg & 3;
    size_t base = (size_t)node * KC + (size_t)rel * Kpad;
#pragma unroll
    for (int j = 0; j < CH; j++) {
        int o = tid + j * 256;
        if (o < D) {
            float v = acc[j] * inv;
            __nv_bfloat16 hi = __float2bfloat16(v);
            outHi[base + o] = hi;
            outLo[base + o] = __float2bfloat16(v - __bfloat162float(hi));
        }
    }
}

// ---------------- mma.sync bf16-split GEMM (single-pass, one sync/chunk) ----------------
// C[m][n] = relu( sum_k A[m][k]*W[n][k] + bias[n] ),  A=Ahi+Alo, W=Whi+Wlo (3-term)
// CTA 128x128, BK=64, 3-stage cp.async (prefetch distance 2, loads issued at top
// of the iteration right after the barrier), 8 warps (2m x 4n), warp tile 64x32.
#define TILE_B  (128 * 128)
#define STAGE_B (4 * TILE_B)         // 64 KB
#define GEMM_SMEM (3 * STAGE_B)      // 192 KB

__global__ void __launch_bounds__(256, 1)
gemm_mma_kernel(const __nv_bfloat16* __restrict__ Ahi, const __nv_bfloat16* __restrict__ Alo,
                const __nv_bfloat16* __restrict__ Bhi, const __nv_bfloat16* __restrict__ Blo,
                int KC, int Nout, const float* __restrict__ bias,
                float* __restrict__ outF,
                __nv_bfloat16* __restrict__ outHi, __nv_bfloat16* __restrict__ outLo,
                int strideO, int colOff)
{
    extern __shared__ char dsm[];
    const uint32_t sbase = smem_to_u32(dsm);
    const int tid = threadIdx.x;
    const int lane = tid & 31;
    const int wid = tid >> 5;
    const int m_off = (wid >> 2) * 64;
    const int n_off = (wid & 3) * 32;
    const int m0 = blockIdx.y * 128;
    const int n0 = blockIdx.x * 128;

    const int arow = lane & 15;
    const uint32_t xorv = (uint32_t)(arow & 7) << 4;
    uint32_t colp[4];
#pragma unroll
    for (int ks = 0; ks < 4; ks++)
        colp[ks] = ((uint32_t)(ks * 32 + ((lane >> 4) * 16))) ^ xorv;
    uint32_t rowA[4], rowB[2];
#pragma unroll
    for (int mi = 0; mi < 4; mi++) rowA[mi] = (uint32_t)(m_off + mi * 16 + arow) * 128u;
#pragma unroll
    for (int nj = 0; nj < 2; nj++) rowB[nj] = (uint32_t)(n_off + nj * 16 + arow) * 128u;

    float acc[4][4][4];
#pragma unroll
    for (int mi = 0; mi < 4; mi++)
#pragma unroll
        for (int nt = 0; nt < 4; nt++)
#pragma unroll
            for (int q = 0; q < 4; q++) acc[mi][nt][q] = 0.f;

    const int chunks = KC >> 6;

    auto load_stage = [&](int slot, int c) {
        const int k0 = c << 6;
        const uint32_t base = sbase + (uint32_t)slot * STAGE_B;
#pragma unroll
        for (int i = 0; i < 16; i++) {
            int idx = tid + i * 256;
            int t = idx >> 10;
            int r = (idx >> 3) & 127;
            int j = idx & 7;
            const __nv_bfloat16* src = (t == 0) ? Ahi : (t == 1) ? Alo : (t == 2) ? Bhi : Blo;
            int row0 = (t < 2) ? m0 : n0;
            CP_ASYNC16(base + (uint32_t)t * TILE_B + SWZ((uint32_t)(r * 128 + j * 16)),
                       (const void*)(src + (size_t)(row0 + r) * KC + k0 + j * 8));
        }
        CP_ASYNC_COMMIT();
    };

    // prologue: 2 stages in flight
    load_stage(0, 0);
    if (chunks > 1) load_stage(1, 1);

    for (int c = 0; c < chunks; c++) {
        // wait until group c complete (leave at most the one trailing group in flight)
        if (c + 1 < chunks) CP_ASYNC_WAIT(1);
        else                CP_ASYNC_WAIT(0);
        __syncthreads();
        // issue loads for chunk c+2 into stage (c+2)%3 == (c-1)%3 — the barrier above
        // proves every warp finished computing chunk c-1, so that stage is free.
        if (c + 2 < chunks) load_stage((c + 2) % 3, c + 2);

        const uint32_t sb = sbase + (uint32_t)(c % 3) * STAGE_B;
#pragma unroll
        for (int ks = 0; ks < 4; ks++) {
            uint32_t ah[4][4], al[4][4];
            uint32_t bh[4][2], bl[4][2];
#pragma unroll
            for (int mi = 0; mi < 4; mi++) {
                ldsm4(ah[mi], sb + rowA[mi] + colp[ks]);
                ldsm4(al[mi], sb + TILE_B + rowA[mi] + colp[ks]);
            }
#pragma unroll
            for (int nj = 0; nj < 2; nj++) {
                uint32_t t4[4];
                ldsm4(t4, sb + 2 * TILE_B + rowB[nj] + colp[ks]);
                bh[2 * nj][0] = t4[0]; bh[2 * nj][1] = t4[2];
                bh[2 * nj + 1][0] = t4[1]; bh[2 * nj + 1][1] = t4[3];
                ldsm4(t4, sb + 3 * TILE_B + rowB[nj] + colp[ks]);
                bl[2 * nj][0] = t4[0]; bl[2 * nj][1] = t4[2];
                bl[2 * nj + 1][0] = t4[1]; bl[2 * nj + 1][1] = t4[3];
            }
#pragma unroll
            for (int mi = 0; mi < 4; mi++)
#pragma unroll
                for (int nt = 0; nt < 4; nt++) {
                    mma16816(acc[mi][nt], ah[mi], bh[nt][0], bh[nt][1]);
                    mma16816(acc[mi][nt], ah[mi], bl[nt][0], bl[nt][1]);
                    mma16816(acc[mi][nt], al[mi], bh[nt][0], bh[nt][1]);
                }
        }
    }

    // ---- epilogue: regs -> smem -> gmem (bias + relu; fp32 and/or bf16 hi/lo) ----
    __syncthreads();   // all warps done with their last stage before smem reuse
    float* sC = (float*)dsm;
#pragma unroll
    for (int mi = 0; mi < 4; mi++)
#pragma unroll
        for (int nt = 0; nt < 4; nt++) {
            int r0 = m_off + mi * 16 + (lane >> 2);
            int c0 = n_off + nt * 8 + (lane & 3) * 2;
            *(float2*)&sC[r0 * 132 + c0] = make_float2(acc[mi][nt][0], acc[mi][nt][1]);
            *(float2*)&sC[(r0 + 8) * 132 + c0] = make_float2(acc[mi][nt][2], acc[mi][nt][3]);
        }
    __syncthreads();
#pragma unroll
    for (int i = 0; i < 64; i++) {
        int idx = tid + i * 256;
        int r = idx >> 7, cc = idx & 127;
        int gm = m0 + r, gn = n0 + cc;
        if (gm < NNODES && gn < Nout) {
            float v = fmaxf(sC[r * 132 + cc] + bias[gn], 0.f);
            if (outF) outF[(size_t)gm * Nout + gn] = v;
            if (outHi) {
                __nv_bfloat16 hi = __float2bfloat16(v);
                size_t o = (size_t)gm * strideO + colOff + gn;
                outHi[o] = hi;
                outLo[o] = __float2bfloat16(v - __bfloat162float(hi));
            }
        }
    }
}

// ---------------- final head: logits + log_softmax ----------------
__global__ void logits_kernel(const float* __restrict__ emb,
                              const float* __restrict__ lin2_w,
                              const float* __restrict__ lin2_b,
                              float* __restrict__ out)
{
    int gtid = blockIdx.x * blockDim.x + threadIdx.x;
    int node = gtid >> 5;
    int lane = gtid & 31;
    if (node >= NNODES) return;
    const float* e = emb + (size_t)node * DIM3;
    float s0 = 0.f, s1 = 0.f;
    for (int k = lane; k < DIM3; k += 32) {
        float v = e[k];
        s0 = fmaf(v, lin2_w[2 * k + 0], s0);
        s1 = fmaf(v, lin2_w[2 * k + 1], s1);
    }
#pragma unroll
    for (int o = 16; o; o >>= 1) {
        s0 += __shfl_down_sync(0xffffffffu, s0, o);
        s1 += __shfl_down_sync(0xffffffffu, s1, o);
    }
    if (lane == 0) {
        s0 += lin2_b[0];
        s1 += lin2_b[1];
        float m = fmaxf(s0, s1);
        float l = m + logf(expf(s0 - m) + expf(s1 - m));
        out[2 * node + 0] = s0 - l;
        out[2 * node + 1] = s1 - l;
    }
}

// ---------------- launch ----------------
extern "C" void kernel_launch(void* const* d_in, const int* in_sizes, int n_in,
                              void* d_out, int out_size)
{
    const float* x       = (const float*)d_in[0];
    const float* gene    = (const float*)d_in[1];
    const float* w_rel1  = (const float*)d_in[2];
    const float* root1   = (const float*)d_in[3];
    const float* b1      = (const float*)d_in[4];
    const float* w_rel2  = (const float*)d_in[5];
    const float* root2   = (const float*)d_in[6];
    const float* b2      = (const float*)d_in[7];
    const float* lin1_w  = (const float*)d_in[8];
    const float* lin1_b  = (const float*)d_in[9];
    const float* lin2_w  = (const float*)d_in[10];
    const float* lin2_b  = (const float*)d_in[11];
    const int*   edge_index = (const int*)d_in[12];
    const int*   edge_type  = (const int*)d_in[13];
    float* out = (float*)d_out;

    __nv_bfloat16 *Xch, *Xcl, *W1h, *W1l, *A1ch, *A1cl, *W2h, *W2l, *A2h, *A2l, *W3h, *W3l;
    float *A1;
    cudaGetSymbolAddress((void**)&Xch, g_Xcat_hi);  cudaGetSymbolAddress((void**)&Xcl, g_Xcat_lo);
    cudaGetSymbolAddress((void**)&W1h, g_W1hi);     cudaGetSymbolAddress((void**)&W1l, g_W1lo);
    cudaGetSymbolAddress((void**)&A1, g_A1);
    cudaGetSymbolAddress((void**)&A1ch, g_A1cat_hi); cudaGetSymbolAddress((void**)&A1cl, g_A1cat_lo);
    cudaGetSymbolAddress((void**)&W2h, g_W2hi);     cudaGetSymbolAddress((void**)&W2l, g_W2lo);
    cudaGetSymbolAddress((void**)&A2h, g_A2hi);     cudaGetSymbolAddress((void**)&A2l, g_A2lo);
    cudaGetSymbolAddress((void**)&W3h, g_W3hi);     cudaGetSymbolAddress((void**)&W3l, g_W3lo);

    cudaFuncSetAttribute(gemm_mma_kernel, cudaFuncAttributeMaxDynamicSharedMemorySize, GEMM_SMEM);

    // 1) weight transposes + splits
    {
        dim3 tb(32, 8);
        transpose_split_kernel<<<dim3(KP1 / 32, NP1 / 32, 5), tb>>>(w_rel1, root1, W1h, W1l, IN_DIM, DIM1, KP1, KC1, NP1);
        transpose_split_kernel<<<dim3(KP2 / 32, NP2 / 32, 5), tb>>>(w_rel2, root2, W2h, W2l, DIM1, DIM2, KP2, KC2, NP2);
        transpose_split_kernel<<<dim3(KP3 / 32, NP3 / 32, 1), tb>>>(nullptr, lin1_w, W3h, W3l, DIM2, DIM3, KP3, KP3, NP3);
    }
    // 2) edge preprocessing
    zero_cnt_kernel<<<(NSEG + 255) / 256, 256>>>();
    count_kernel<<<(N_EDGES + 255) / 256, 256>>>(edge_index, edge_type);
    scan_kernel<<<1, 1024>>>();
    fill_kernel<<<(N_EDGES + 255) / 256, 256>>>(edge_index, edge_type);

    // 3) layer-1 input assembly
    {
        size_t tot = (size_t)NNODES * IN_DIM;
        xfill_kernel<<<(unsigned)((tot + 255) / 256), 256>>>(x, gene);
    }
    agg_seg_kernel<7><<<NSEG, 256>>>(x, gene, N_DRUGS, IN_DIM, KP1, KC1, Xch, Xcl);

    // 4) layer-1 GEMM: A1 = relu(Xcat @ W1cat^T + b1); emit hi/lo into A1cat root slot
    gemm_mma_kernel<<<dim3(NP1 / 128, MPAD / 128), 256, GEMM_SMEM>>>(
        Xch, Xcl, W1h, W1l, KC1, DIM1, b1, A1, A1ch, A1cl, KC2, 4 * KP2);

    // 5) layer-2 input assembly
    agg_seg_kernel<6><<<NSEG, 256>>>(A1, A1, NNODES, DIM1, KP2, KC2, A1ch, A1cl);

    // 6) layer-2 GEMM
    gemm_mma_kernel<<<dim3(NP2 / 128, MPAD / 128), 256, GEMM_SMEM>>>(
        A1ch, A1cl, W2h, W2l, KC2, DIM2, b2, nullptr, A2h, A2l, KP3, 0);

    // 7) lin1 -> emb in output buffer
    float* emb = out + 2 * NNODES;
    gemm_mma_kernel<<<dim3(NP3 / 128, MPAD / 128), 256, GEMM_SMEM>>>(
        A2h, A2l, W3h, W3l, KP3, DIM3, lin1_b, emb, nullptr, nullptr, 0, 0);

    // 8) lin2 + log_softmax
    logits_kernel<<<(NNODES * 32 + 255) / 256, 256>>>(emb, lin2_w, lin2_b, out);
}

// round 7
// speedup vs baseline: 1.1556x; 1.0400x over previous
#include <cuda_runtime.h>
#include <cuda_bf16.h>
#include <cstdint>
#include <math.h>

// ---------------- problem constants ----------------
#define N_DRUGS   4000
#define N_GENES   4264
#define NNODES    8264
#define IN_DIM    1613
#define DIM1      1340
#define DIM2      920
#define DIM3      740
#define N_REL     4
#define N_EDGES   100000
#define NSEG      (NNODES * N_REL)     // 33056

#define MPAD      8320                 // 65 * 128
#define KP1       1664                 // pad(1613, 64)
#define KP2       1344                 // pad(1340, 64)
#define KP3       960                  // pad(920, 64)
#define KC1       (5 * KP1)            // 8320
#define KC2       (5 * KP2)            // 6720
#define NP1       1408
#define NP2       1024
#define NP3       768

// ---------------- device scratch ----------------
__device__ __nv_bfloat16 g_Xcat_hi[(size_t)MPAD * KC1];
__device__ __nv_bfloat16 g_Xcat_lo[(size_t)MPAD * KC1];
__device__ __nv_bfloat16 g_W1hi[(size_t)NP1 * KC1];
__device__ __nv_bfloat16 g_W1lo[(size_t)NP1 * KC1];
__device__ float         g_A1[(size_t)NNODES * DIM1];
__device__ __nv_bfloat16 g_A1cat_hi[(size_t)MPAD * KC2];
__device__ __nv_bfloat16 g_A1cat_lo[(size_t)MPAD * KC2];
__device__ __nv_bfloat16 g_W2hi[(size_t)NP2 * KC2];
__device__ __nv_bfloat16 g_W2lo[(size_t)NP2 * KC2];
__device__ __nv_bfloat16 g_A2hi[(size_t)MPAD * KP3];
__device__ __nv_bfloat16 g_A2lo[(size_t)MPAD * KP3];
__device__ __nv_bfloat16 g_W3hi[(size_t)NP3 * KP3];
__device__ __nv_bfloat16 g_W3lo[(size_t)NP3 * KP3];
__device__ int g_cnt[NSEG];
__device__ int g_seg_start[NSEG + 1];
__device__ int g_cursor[NSEG];
__device__ int g_esrc[N_EDGES];

// ---------------- PTX helpers (plain sm_80+ instructions only) ----------------
__device__ __forceinline__ uint32_t smem_to_u32(const void* p) {
    uint32_t a;
    asm("{ .reg .u64 t; cvta.to.shared.u64 t, %1; cvt.u32.u64 %0, t; }" : "=r"(a) : "l"(p));
    return a;
}
#define CP_ASYNC16(dst, src) \
    asm volatile("cp.async.cg.shared.global [%0], [%1], 16;" :: "r"(dst), "l"(src) : "memory")
#define CP_ASYNC_COMMIT() asm volatile("cp.async.commit_group;" ::: "memory")
#define CP_ASYNC_WAIT(n)  asm volatile("cp.async.wait_group %0;" :: "n"(n) : "memory")

__device__ __forceinline__ void ldsm4(uint32_t (&r)[4], uint32_t addr) {
    asm volatile("ldmatrix.sync.aligned.m8n8.x4.shared.b16 {%0,%1,%2,%3}, [%4];"
                 : "=r"(r[0]), "=r"(r[1]), "=r"(r[2]), "=r"(r[3]) : "r"(addr));
}
__device__ __forceinline__ void mma16816(float (&d)[4], const uint32_t (&a)[4],
                                         uint32_t b0, uint32_t b1) {
    asm volatile(
        "mma.sync.aligned.m16n8k16.row.col.f32.bf16.bf16.f32 "
        "{%0,%1,%2,%3}, {%4,%5,%6,%7}, {%8,%9}, {%0,%1,%2,%3};"
        : "+f"(d[0]), "+f"(d[1]), "+f"(d[2]), "+f"(d[3])
        : "r"(a[0]), "r"(a[1]), "r"(a[2]), "r"(a[3]), "r"(b0), "r"(b1));
}
#define SWZ(off) ((off) ^ (((off) >> 3) & 0x70))

// ---------------- prep: x -> Xcat root slot (bf16 hi/lo) ----------------
__global__ void xfill_kernel(const float* __restrict__ x, const float* __restrict__ gene)
{
    size_t i = (size_t)blockIdx.x * blockDim.x + threadIdx.x;
    const size_t TOT = (size_t)NNODES * IN_DIM;
    if (i >= TOT) return;
    int node = (int)(i / IN_DIM);
    int k = (int)(i % IN_DIM);
    float v = (node < N_DRUGS) ? x[(size_t)node * IN_DIM + k]
                               : gene[(size_t)(node - N_DRUGS) * IN_DIM + k];
    __nv_bfloat16 hi = __float2bfloat16(v);
    size_t o = (size_t)node * KC1 + 4 * KP1 + k;
    g_Xcat_hi[o] = hi;
    g_Xcat_lo[o] = __float2bfloat16(v - __bfloat162float(hi));
}

// transpose W[K][N] (z slabs) -> Wcat[n][z*Kpad + k] hi/lo, zero-padded
__global__ void transpose_split_kernel(const float* __restrict__ Wrel,
                                       const float* __restrict__ Wroot,
                                       __nv_bfloat16* __restrict__ Thi,
                                       __nv_bfloat16* __restrict__ Tlo,
                                       int K, int N, int Kpad, int KC, int Npad)
{
    __shared__ float t[32][33];
    int z = blockIdx.z;
    const float* W = (Wrel != nullptr && z < N_REL) ? (Wrel + (size_t)z * K * N) : Wroot;
    int k0 = blockIdx.x * 32;
    int n0 = blockIdx.y * 32;
    int tx = threadIdx.x, ty = threadIdx.y;
#pragma unroll
    for (int i = 0; i < 4; i++) {
        int k = k0 + ty + i * 8;
        int n = n0 + tx;
        t[ty + i * 8][tx] = (k < K && n < N) ? W[(size_t)k * N + n] : 0.f;
    }
    __syncthreads();
#pragma unroll
    for (int i = 0; i < 4; i++) {
        int n = n0 + ty + i * 8;
        int kk = k0 + tx;
        float v = t[tx][ty + i * 8];
        __nv_bfloat16 hi = __float2bfloat16(v);
        size_t o = (size_t)n * KC + (size_t)z * Kpad + kk;
        Thi[o] = hi;
        Tlo[o] = __float2bfloat16(v - __bfloat162float(hi));
    }
}

// ---------------- edge preprocessing ----------------
__global__ void zero_cnt_kernel()
{
    int i = blockIdx.x * blockDim.x + threadIdx.x;
    if (i < NSEG) g_cnt[i] = 0;
}
__global__ void count_kernel(const int* __restrict__ edge_index, const int* __restrict__ edge_type)
{
    int e = blockIdx.x * blockDim.x + threadIdx.x;
    if (e >= N_EDGES) return;
    atomicAdd(&g_cnt[edge_index[N_EDGES + e] * N_REL + edge_type[e]], 1);
}
__global__ void scan_kernel()
{
    __shared__ int part[1024];
    const int CHK = (NSEG + 1023) / 1024;
    int tid = threadIdx.x;
    int degs[CHK];
    int mysum = 0;
#pragma unroll
    for (int i = 0; i < CHK; i++) {
        int d = tid * CHK + i;
        int dg = (d < NSEG) ? g_cnt[d] : 0;
        degs[i] = dg;
        mysum += dg;
    }
    part[tid] = mysum;
    __syncthreads();
    if (tid == 0) {
        int run = 0;
        for (int t = 0; t < 1024; t++) { int v = part[t]; part[t] = run; run += v; }
        g_seg_start[NSEG] = run;
    }
    __syncthreads();
    int off = part[tid];
#pragma unroll
    for (int i = 0; i < CHK; i++) {
        int d = tid * CHK + i;
        if (d < NSEG) { g_seg_start[d] = off; g_cursor[d] = off; off += degs[i]; }
    }
}
__global__ void fill_kernel(const int* __restrict__ edge_index, const int* __restrict__ edge_type)
{
    int e = blockIdx.x * blockDim.x + threadIdx.x;
    if (e >= N_EDGES) return;
    int seg = edge_index[N_EDGES + e] * N_REL + edge_type[e];
    int pos = atomicAdd(&g_cursor[seg], 1);
    g_esrc[pos] = edge_index[e];
}

// ---------------- segment-mean aggregation, emits bf16 hi/lo ----------------
template <int CH>
__global__ void agg_seg_kernel(const float* __restrict__ src0, const float* __restrict__ src1,
                               int splitRow, int D, int Kpad, int KC,
                               __nv_bfloat16* __restrict__ outHi, __nv_bfloat16* __restrict__ outLo)
{
    int seg = blockIdx.x;
    int s = g_seg_start[seg];
    int e = g_seg_start[seg + 1];
    if (s == e) return;
    int tid = threadIdx.x;
    float acc[CH];
#pragma unroll
    for (int j = 0; j < CH; j++) acc[j] = 0.f;
    for (int p = s; p < e; p++) {
        int sn = g_esrc[p];
        const float* row = (sn < splitRow) ? (src0 + (size_t)sn * D)
                                           : (src1 + (size_t)(sn - splitRow) * D);
#pragma unroll
        for (int j = 0; j < CH; j++) {
            int o = tid + j * 256;
            if (o < D) acc[j] += row[o];
        }
    }
    float inv = 1.0f / (float)(e - s);
    int node = seg >> 2, rel = seg & 3;
    size_t base = (size_t)node * KC + (size_t)rel * Kpad;
#pragma unroll
    for (int j = 0; j < CH; j++) {
        int o = tid + j * 256;
        if (o < D) {
            float v = acc[j] * inv;
            __nv_bfloat16 hi = __float2bfloat16(v);
            outHi[base + o] = hi;
            outLo[base + o] = __float2bfloat16(v - __bfloat162float(hi));
        }
    }
}

// ---------------- mma.sync bf16-split GEMM: 512 threads, warp tile 32x32 ----------------
// C[m][n] = relu( sum_k A[m][k]*W[n][k] + bias[n] ),  A=Ahi+Alo, W=Whi+Wlo (3-term)
// CTA tile 128x128, BK=64, 3-stage cp.async, 16 warps (4m x 4n) -> 4 warps/SMSP.
#define TILE_B  (128 * 128)
#define STAGE_B (4 * TILE_B)         // 64 KB
#define GEMM_SMEM (3 * STAGE_B)      // 192 KB
#define GTHREADS 512

__global__ void __launch_bounds__(GTHREADS, 1)
gemm_mma_kernel(const __nv_bfloat16* __restrict__ Ahi, const __nv_bfloat16* __restrict__ Alo,
                const __nv_bfloat16* __restrict__ Bhi, const __nv_bfloat16* __restrict__ Blo,
                int KC, int Nout, const float* __restrict__ bias,
                float* __restrict__ outF,
                __nv_bfloat16* __restrict__ outHi, __nv_bfloat16* __restrict__ outLo,
                int strideO, int colOff)
{
    extern __shared__ char dsm[];
    const uint32_t sbase = smem_to_u32(dsm);
    const int tid = threadIdx.x;
    const int lane = tid & 31;
    const int wid = tid >> 5;                 // 0..15
    const int m_off = (wid >> 2) * 32;        // 4 m-groups
    const int n_off = (wid & 3) * 32;         // 4 n-groups
    const int m0 = blockIdx.y * 128;
    const int n0 = blockIdx.x * 128;

    const int arow = lane & 15;
    const uint32_t xorv = (uint32_t)(arow & 7) << 4;
    uint32_t colp[4];
#pragma unroll
    for (int ks = 0; ks < 4; ks++)
        colp[ks] = ((uint32_t)(ks * 32 + ((lane >> 4) * 16))) ^ xorv;
    uint32_t rowA[2], rowB[2];
#pragma unroll
    for (int mi = 0; mi < 2; mi++) rowA[mi] = (uint32_t)(m_off + mi * 16 + arow) * 128u;
#pragma unroll
    for (int nj = 0; nj < 2; nj++) rowB[nj] = (uint32_t)(n_off + nj * 16 + arow) * 128u;

    float acc[2][4][4];
#pragma unroll
    for (int mi = 0; mi < 2; mi++)
#pragma unroll
        for (int nt = 0; nt < 4; nt++)
#pragma unroll
            for (int q = 0; q < 4; q++) acc[mi][nt][q] = 0.f;

    const int chunks = KC >> 6;

    auto load_stage = [&](int slot, int c) {
        const int k0 = c << 6;
        const uint32_t base = sbase + (uint32_t)slot * STAGE_B;
#pragma unroll
        for (int i = 0; i < 8; i++) {
            int idx = tid + i * GTHREADS;
            int t = idx >> 10;
            int r = (idx >> 3) & 127;
            int j = idx & 7;
            const __nv_bfloat16* src = (t == 0) ? Ahi : (t == 1) ? Alo : (t == 2) ? Bhi : Blo;
            int row0 = (t < 2) ? m0 : n0;
            CP_ASYNC16(base + (uint32_t)t * TILE_B + SWZ((uint32_t)(r * 128 + j * 16)),
                       (const void*)(src + (size_t)(row0 + r) * KC + k0 + j * 8));
        }
        CP_ASYNC_COMMIT();
    };

    load_stage(0, 0);
    if (chunks > 1) load_stage(1, 1);

    for (int c = 0; c < chunks; c++) {
        if (c + 1 < chunks) CP_ASYNC_WAIT(1);
        else                CP_ASYNC_WAIT(0);
        __syncthreads();
        if (c + 2 < chunks) load_stage((c + 2) % 3, c + 2);

        const uint32_t sb = sbase + (uint32_t)(c % 3) * STAGE_B;
#pragma unroll
        for (int ks = 0; ks < 4; ks++) {
            uint32_t ah[2][4], al[2][4];
            uint32_t bh[4][2], bl[4][2];
#pragma unroll
            for (int mi = 0; mi < 2; mi++) {
                ldsm4(ah[mi], sb + rowA[mi] + colp[ks]);
                ldsm4(al[mi], sb + TILE_B + rowA[mi] + colp[ks]);
            }
#pragma unroll
            for (int nj = 0; nj < 2; nj++) {
                uint32_t t4[4];
                ldsm4(t4, sb + 2 * TILE_B + rowB[nj] + colp[ks]);
                bh[2 * nj][0] = t4[0]; bh[2 * nj][1] = t4[2];
                bh[2 * nj + 1][0] = t4[1]; bh[2 * nj + 1][1] = t4[3];
                ldsm4(t4, sb + 3 * TILE_B + rowB[nj] + colp[ks]);
                bl[2 * nj][0] = t4[0]; bl[2 * nj][1] = t4[2];
                bl[2 * nj + 1][0] = t4[1]; bl[2 * nj + 1][1] = t4[3];
            }
#pragma unroll
            for (int mi = 0; mi < 2; mi++)
#pragma unroll
                for (int nt = 0; nt < 4; nt++) {
                    mma16816(acc[mi][nt], ah[mi], bh[nt][0], bh[nt][1]);
                    mma16816(acc[mi][nt], ah[mi], bl[nt][0], bl[nt][1]);
                    mma16816(acc[mi][nt], al[mi], bh[nt][0], bh[nt][1]);
                }
        }
    }

    // ---- epilogue: regs -> smem -> gmem (bias + relu; fp32 and/or bf16 hi/lo) ----
    __syncthreads();
    float* sC = (float*)dsm;
#pragma unroll
    for (int mi = 0; mi < 2; mi++)
#pragma unroll
        for (int nt = 0; nt < 4; nt++) {
            int r0 = m_off + mi * 16 + (lane >> 2);
            int c0 = n_off + nt * 8 + (lane & 3) * 2;
            *(float2*)&sC[r0 * 132 + c0] = make_float2(acc[mi][nt][0], acc[mi][nt][1]);
            *(float2*)&sC[(r0 + 8) * 132 + c0] = make_float2(acc[mi][nt][2], acc[mi][nt][3]);
        }
    __syncthreads();
#pragma unroll
    for (int i = 0; i < 32; i++) {
        int idx = tid + i * GTHREADS;
        int r = idx >> 7, cc = idx & 127;
        int gm = m0 + r, gn = n0 + cc;
        if (gm < NNODES && gn < Nout) {
            float v = fmaxf(sC[r * 132 + cc] + bias[gn], 0.f);
            if (outF) outF[(size_t)gm * Nout + gn] = v;
            if (outHi) {
                __nv_bfloat16 hi = __float2bfloat16(v);
                size_t o = (size_t)gm * strideO + colOff + gn;
                outHi[o] = hi;
                outLo[o] = __float2bfloat16(v - __bfloat162float(hi));
            }
        }
    }
}

// ---------------- final head: logits + log_softmax ----------------
__global__ void logits_kernel(const float* __restrict__ emb,
                              const float* __restrict__ lin2_w,
                              const float* __restrict__ lin2_b,
                              float* __restrict__ out)
{
    int gtid = blockIdx.x * blockDim.x + threadIdx.x;
    int node = gtid >> 5;
    int lane = gtid & 31;
    if (node >= NNODES) return;
    const float* e = emb + (size_t)node * DIM3;
    float s0 = 0.f, s1 = 0.f;
    for (int k = lane; k < DIM3; k += 32) {
        float v = e[k];
        s0 = fmaf(v, lin2_w[2 * k + 0], s0);
        s1 = fmaf(v, lin2_w[2 * k + 1], s1);
    }
#pragma unroll
    for (int o = 16; o; o >>= 1) {
        s0 += __shfl_down_sync(0xffffffffu, s0, o);
        s1 += __shfl_down_sync(0xffffffffu, s1, o);
    }
    if (lane == 0) {
        s0 += lin2_b[0];
        s1 += lin2_b[1];
        float m = fmaxf(s0, s1);
        float l = m + logf(expf(s0 - m) + expf(s1 - m));
        out[2 * node + 0] = s0 - l;
        out[2 * node + 1] = s1 - l;
    }
}

// ---------------- launch ----------------
extern "C" void kernel_launch(void* const* d_in, const int* in_sizes, int n_in,
                              void* d_out, int out_size)
{
    const float* x       = (const float*)d_in[0];
    const float* gene    = (const float*)d_in[1];
    const float* w_rel1  = (const float*)d_in[2];
    const float* root1   = (const float*)d_in[3];
    const float* b1      = (const float*)d_in[4];
    const float* w_rel2  = (const float*)d_in[5];
    const float* root2   = (const float*)d_in[6];
    const float* b2      = (const float*)d_in[7];
    const float* lin1_w  = (const float*)d_in[8];
    const float* lin1_b  = (const float*)d_in[9];
    const float* lin2_w  = (const float*)d_in[10];
    const float* lin2_b  = (const float*)d_in[11];
    const int*   edge_index = (const int*)d_in[12];
    const int*   edge_type  = (const int*)d_in[13];
    float* out = (float*)d_out;

    __nv_bfloat16 *Xch, *Xcl, *W1h, *W1l, *A1ch, *A1cl, *W2h, *W2l, *A2h, *A2l, *W3h, *W3l;
    float *A1;
    cudaGetSymbolAddress((void**)&Xch, g_Xcat_hi);  cudaGetSymbolAddress((void**)&Xcl, g_Xcat_lo);
    cudaGetSymbolAddress((void**)&W1h, g_W1hi);     cudaGetSymbolAddress((void**)&W1l, g_W1lo);
    cudaGetSymbolAddress((void**)&A1, g_A1);
    cudaGetSymbolAddress((void**)&A1ch, g_A1cat_hi); cudaGetSymbolAddress((void**)&A1cl, g_A1cat_lo);
    cudaGetSymbolAddress((void**)&W2h, g_W2hi);     cudaGetSymbolAddress((void**)&W2l, g_W2lo);
    cudaGetSymbolAddress((void**)&A2h, g_A2hi);     cudaGetSymbolAddress((void**)&A2l, g_A2lo);
    cudaGetSymbolAddress((void**)&W3h, g_W3hi);     cudaGetSymbolAddress((void**)&W3l, g_W3lo);

    cudaFuncSetAttribute(gemm_mma_kernel, cudaFuncAttributeMaxDynamicSharedMemorySize, GEMM_SMEM);

    // 1) weight transposes + splits
    {
        dim3 tb(32, 8);
        transpose_split_kernel<<<dim3(KP1 / 32, NP1 / 32, 5), tb>>>(w_rel1, root1, W1h, W1l, IN_DIM, DIM1, KP1, KC1, NP1);
        transpose_split_kernel<<<dim3(KP2 / 32, NP2 / 32, 5), tb>>>(w_rel2, root2, W2h, W2l, DIM1, DIM2, KP2, KC2, NP2);
        transpose_split_kernel<<<dim3(KP3 / 32, NP3 / 32, 1), tb>>>(nullptr, lin1_w, W3h, W3l, DIM2, DIM3, KP3, KP3, NP3);
    }
    // 2) edge preprocessing
    zero_cnt_kernel<<<(NSEG + 255) / 256, 256>>>();
    count_kernel<<<(N_EDGES + 255) / 256, 256>>>(edge_index, edge_type);
    scan_kernel<<<1, 1024>>>();
    fill_kernel<<<(N_EDGES + 255) / 256, 256>>>(edge_index, edge_type);

    // 3) layer-1 input assembly
    {
        size_t tot = (size_t)NNODES * IN_DIM;
        xfill_kernel<<<(unsigned)((tot + 255) / 256), 256>>>(x, gene);
    }
    agg_seg_kernel<7><<<NSEG, 256>>>(x, gene, N_DRUGS, IN_DIM, KP1, KC1, Xch, Xcl);

    // 4) layer-1 GEMM: A1 = relu(Xcat @ W1cat^T + b1); emit hi/lo into A1cat root slot
    gemm_mma_kernel<<<dim3(NP1 / 128, MPAD / 128), GTHREADS, GEMM_SMEM>>>(
        Xch, Xcl, W1h, W1l, KC1, DIM1, b1, A1, A1ch, A1cl, KC2, 4 * KP2);

    // 5) layer-2 input assembly
    agg_seg_kernel<6><<<NSEG, 256>>>(A1, A1, NNODES, DIM1, KP2, KC2, A1ch, A1cl);

    // 6) layer-2 GEMM
    gemm_mma_kernel<<<dim3(NP2 / 128, MPAD / 128), GTHREADS, GEMM_SMEM>>>(
        A1ch, A1cl, W2h, W2l, KC2, DIM2, b2, nullptr, A2h, A2l, KP3, 0);

    // 7) lin1 -> emb in output buffer
    float* emb = out + 2 * NNODES;
    gemm_mma_kernel<<<dim3(NP3 / 128, MPAD / 128), GTHREADS, GEMM_SMEM>>>(
        A2h, A2l, W3h, W3l, KP3, DIM3, lin1_b, emb, nullptr, nullptr, 0, 0);

    // 8) lin2 + log_softmax
    logits_kernel<<<(NNODES * 32 + 255) / 256, 256>>>(emb, lin2_w, lin2_b, out);
}